// round 4
// baseline (speedup 1.0000x reference)
#include <cuda_runtime.h>

// LegoConv2d on GB300: per-(b,h) slab, one merged GEMM  feat[64n x 224(i,w)] =
// lego[64 x 192] @ X[192 x 224], then fused one-hot gather epilogue.
//
// Shapes: x (32,256,56,56) f32, lego (64,64,3,1), aux_* (4,256,64,1,1).
// out (32,256,19,58) f32. Out cols 0 and 57 are exactly zero (width-1 kernel
// over width padding); stride-3 height conv is non-overlapping.

#define BATCH   32
#define IN_C    256
#define OUT_C   256
#define NSPLIT  4
#define NLEGO   64
#define BASIC_C 64
#define HIN     56
#define WIN     56
#define HOUT    19
#define WOUT    58
#define KTOT    192           // BASIC_C * 3 taps
#define KC      96            // K-chunk staged in smem
#define NCHUNK  2
#define NCOL    224           // NSPLIT * 56 merged GEMM columns
#define LSTRIDE 68            // padded lego_s row (68*4B = 272B, 16B aligned, bank-safe)

#define SMEM_FLOATS (KC*LSTRIDE + KC*NCOL)   // 6528 + 21504 = 28032 floats = 112128 B

__device__ int   g_idx[NSPLIT * OUT_C];
__device__ float g_coef[NSPLIT * OUT_C];

// -------- prep: argmax over n (first-max, matching jnp.argmax) + coefficient pick
__global__ void prep_kernel(const float* __restrict__ coefs,
                            const float* __restrict__ comb) {
    int t = blockIdx.x * blockDim.x + threadIdx.x;   // t = i*256 + o
    if (t >= NSPLIT * OUT_C) return;
    const float* c = comb + (size_t)t * NLEGO;
    float bv = c[0];
    int bi = 0;
    #pragma unroll
    for (int n = 1; n < NLEGO; n++) {
        float v = c[n];
        if (v > bv) { bv = v; bi = n; }
    }
    g_idx[t]  = bi;
    g_coef[t] = coefs[(size_t)t * NLEGO + bi];
}

// -------- main: one block per (h, b); 256 threads; 8n x 7col register tile/thread
extern __shared__ float smem[];

__global__ __launch_bounds__(256, 2)
void main_kernel(const float* __restrict__ x,
                 const float* __restrict__ lego,
                 float* __restrict__ out) {
    const int h = blockIdx.x;   // 0..18
    const int b = blockIdx.y;   // 0..31
    const int t = threadIdx.x;

    float* lego_s = smem;                    // [KC][LSTRIDE]  (lego_s[kk][n])
    float* X_s    = smem + KC * LSTRIDE;     // [KC][NCOL]     (X_s[kk][i*56+w])

    const int wg = t & 31;    // column group: cols [7*wg, 7*wg+7)
    const int ng = t >> 5;    // row group:    rows [8*ng, 8*ng+8)   (warp-uniform!)

    float acc[8][7];
    #pragma unroll
    for (int r = 0; r < 8; r++)
        #pragma unroll
        for (int j = 0; j < 7; j++) acc[r][j] = 0.f;

    for (int kc = 0; kc < NCHUNK; kc++) {
        const int k0 = kc * KC;

        // ---- stage lego chunk transposed: lego_s[kk][n] = lego[n][k0+kk]
        // gmem reads coalesced in 96-float runs; STS 4-way conflict (one-time, tiny)
        for (int s = t; s < KC * NLEGO; s += 256) {
            int n  = s / KC;
            int kk = s - n * KC;
            lego_s[kk * LSTRIDE + n] = lego[n * KTOT + k0 + kk];
        }

        // ---- stage X chunk: X_s[kk][i*56+w] = x[b, i*64+c, 3h+kh-1, w],
        //      where k0+kk = c*3 + kh. Only h==0,kh==0 hits the zero pad row.
        for (int s = t; s < KC * NCOL; s += 256) {
            int row = s / 56;          // row = kk*4 + i
            int w   = s - row * 56;
            int kk  = row >> 2;
            int i   = row & 3;
            int k   = k0 + kk;
            int c   = k / 3;
            int kh  = k - c * 3;
            int y   = 3 * h + kh - 1;  // always <= 55
            float v = 0.f;
            if (y >= 0)
                v = x[((size_t)(b * IN_C + i * BASIC_C + c) * HIN + y) * WIN + w];
            X_s[kk * NCOL + i * 56 + w] = v;
        }
        __syncthreads();

        // ---- GEMM accumulate over this K chunk.
        // a-loads: warp-uniform LDS.128 broadcasts (ng uniform per warp).
        // b-loads: stride-7 per lane -> conflict-free (gcd(7,32)=1).
        const float* lp = lego_s + 8 * ng;
        const float* xp = X_s + 7 * wg;
        #pragma unroll 2
        for (int kk = 0; kk < KC; kk++) {
            float4 a0 = *(const float4*)(lp + kk * LSTRIDE);
            float4 a1 = *(const float4*)(lp + kk * LSTRIDE + 4);
            float bb[7];
            #pragma unroll
            for (int j = 0; j < 7; j++) bb[j] = xp[kk * NCOL + j];
            float ar[8] = {a0.x, a0.y, a0.z, a0.w, a1.x, a1.y, a1.z, a1.w};
            #pragma unroll
            for (int r = 0; r < 8; r++)
                #pragma unroll
                for (int j = 0; j < 7; j++)
                    acc[r][j] = fmaf(ar[r], bb[j], acc[r][j]);
        }
        __syncthreads();   // all reads done before next chunk / feat reuse
    }

    // ---- dump feat into smem (reuse X_s region): feat_s[n][i*56+w]
    float* feat_s = X_s;   // 64*224 = 14336 floats <= 21504 available
    #pragma unroll
    for (int r = 0; r < 8; r++)
        #pragma unroll
        for (int j = 0; j < 7; j++)
            feat_s[(8 * ng + r) * NCOL + 7 * wg + j] = acc[r][j];
    __syncthreads();

    // ---- fused gather epilogue: out[b,o,h,w+1] = sum_i coef[i,o]*feat[idx[i,o]][i,w]
    for (int s = t; s < OUT_C * 56; s += 256) {
        int o = s / 56;
        int w = s - o * 56;
        float v = 0.f;
        #pragma unroll
        for (int i = 0; i < NSPLIT; i++) {
            int   id = g_idx[i * OUT_C + o];
            float cf = g_coef[i * OUT_C + o];
            v = fmaf(cf, feat_s[id * NCOL + i * 56 + w], v);
        }
        out[((size_t)(b * OUT_C + o) * HOUT + h) * WOUT + (w + 1)] = v;
    }
    // zero borders (w = 0 and w = 57): exact zeros in the reference
    for (int s = t; s < OUT_C * 2; s += 256) {
        int o  = s >> 1;
        int ww = (s & 1) ? (WOUT - 1) : 0;
        out[((size_t)(b * OUT_C + o) * HOUT + h) * WOUT + ww] = 0.f;
    }
}

extern "C" void kernel_launch(void* const* d_in, const int* in_sizes, int n_in,
                              void* d_out, int out_size) {
    const float* x     = (const float*)d_in[0];   // 32*256*56*56
    const float* lego  = (const float*)d_in[1];   // 64*64*3*1
    const float* coefs = (const float*)d_in[2];   // 4*256*64
    const float* comb  = (const float*)d_in[3];   // 4*256*64
    float* out = (float*)d_out;                   // 32*256*19*58

    (void)in_sizes; (void)n_in; (void)out_size;

    cudaFuncSetAttribute(main_kernel,
                         cudaFuncAttributeMaxDynamicSharedMemorySize,
                         SMEM_FLOATS * (int)sizeof(float));

    prep_kernel<<<4, 256>>>(coefs, comb);
    main_kernel<<<dim3(HOUT, BATCH), 256, SMEM_FLOATS * (int)sizeof(float)>>>(x, lego, out);
}